// round 16
// baseline (speedup 1.0000x reference)
#include <cuda_runtime.h>
#include <cuda_fp16.h>

// ExpFlow: scaling-and-squaring exponentiation of a 3D velocity field.
// x: [N=2, C=3, D=128, H=128, W=128] fp32 -> out same shape.
//
// u = x/32 (channels-last); 5x: u <- u + trilinear_sample(u, id + u),
// border clamp, align_corners=True (sample point = voxel + u*0.5*(size-1)).
//
// R15 scheme (R14 ncu: L1=65%, DRAM=46%, issue=47% -> latency-bound):
//   - 2 voxels per thread (x-pairs): 16 gather loads in flight, halved issue
//     overhead, same L1 line footprint.
//   - fp32 master as SoA 3 planes (12B/voxel, kills the dead float4 w-lane):
//     float2 coalesced center reads/writes per plane.
//   - fp16 half4 shadow (8B/voxel) for the 8 corner gathers only; pair
//     shadow writes fused into one 16B uint4 store.

#define NB 2
#define DD 128
#define HH 128
#define WW 128
#define HW (HH * WW)
#define DHW (DD * HH * WW)
#define NVOX (NB * DHW)
#define NPAIR (NVOX / 2)

// fp32 master ping-pong, SoA planes (16 MB each, 96 MB total)
__device__ float g_mx0[NVOX], g_my0[NVOX], g_mz0[NVOX];
__device__ float g_mx1[NVOX], g_my1[NVOX], g_mz1[NVOX];
// fp16 gather shadow ping-pong (32 MB each); uint2 = {h2(x,y), h2(z,0)}
__device__ uint2 g_h0[NVOX];
__device__ uint2 g_h1[NVOX];

__device__ __forceinline__ uint2 pack_h4(float x, float y, float z) {
    uint2 r;
    __half2 xy = __floats2half2_rn(x, y);
    __half2 zw = __floats2half2_rn(z, 0.0f);
    r.x = *reinterpret_cast<unsigned*>(&xy);
    r.y = *reinterpret_cast<unsigned*>(&zw);
    return r;
}

__device__ __forceinline__ float3 unpack_h4(uint2 raw) {
    __half2 xy = *reinterpret_cast<__half2*>(&raw.x);
    __half2 zw = *reinterpret_cast<__half2*>(&raw.y);
    float2 f = __half22float2(xy);
    return make_float3(f.x, f.y, __low2float(zw));
}

__device__ __forceinline__ float3 lerp3(float3 a, float3 b, float w) {
    float iw = 1.0f - w;
    return make_float3(a.x * iw + b.x * w, a.y * iw + b.y * w, a.z * iw + b.z * w);
}

// ---------------------------------------------------------------------------
// Init: u0 = moveaxis(x,1,-1) / 32 -> SoA master + fp16 shadow. 2 voxels/thread.
// ---------------------------------------------------------------------------
__global__ void __launch_bounds__(256) expflow_init(const float* __restrict__ x,
                                                    float* __restrict__ mx,
                                                    float* __restrict__ my,
                                                    float* __restrict__ mz,
                                                    uint2* __restrict__ h16) {
    int t = blockIdx.x * blockDim.x + threadIdx.x;
    if (t >= NPAIR) return;
    int p = t * 2;
    int n = p / DHW;
    int s = p - n * DHW;
    const float* base = x + (size_t)n * 3 * DHW + s;
    const float sc = 1.0f / 32.0f;  // SCALE=1, STEPS=5
    float2 vx = *reinterpret_cast<const float2*>(base);
    float2 vy = *reinterpret_cast<const float2*>(base + DHW);
    float2 vz = *reinterpret_cast<const float2*>(base + 2 * DHW);
    vx.x *= sc; vx.y *= sc;
    vy.x *= sc; vy.y *= sc;
    vz.x *= sc; vz.y *= sc;
    *reinterpret_cast<float2*>(mx + p) = vx;
    *reinterpret_cast<float2*>(my + p) = vy;
    *reinterpret_cast<float2*>(mz + p) = vz;
    uint2 h0 = pack_h4(vx.x, vy.x, vz.x);
    uint2 h1 = pack_h4(vx.y, vy.y, vz.y);
    uint4 hp = make_uint4(h0.x, h0.y, h1.x, h1.y);
    *reinterpret_cast<uint4*>(h16 + p) = hp;
}

// ---------------------------------------------------------------------------
// One squaring step, 2 voxels/thread: out = u + trilinear(shadow, id + u).
// ---------------------------------------------------------------------------
__device__ __forceinline__ float3 sample_shadow(const uint2* __restrict__ hb,
                                                int xx, int yy, int zz,
                                                float ux, float uy, float uz) {
    float px = fminf(fmaxf((float)xx + ux * (0.5f * (WW - 1)), 0.0f), (float)(WW - 1));
    float py = fminf(fmaxf((float)yy + uy * (0.5f * (HH - 1)), 0.0f), (float)(HH - 1));
    float pz = fminf(fmaxf((float)zz + uz * (0.5f * (DD - 1)), 0.0f), (float)(DD - 1));

    float x0f = floorf(px), y0f = floorf(py), z0f = floorf(pz);
    float wx = px - x0f, wy = py - y0f, wz = pz - z0f;

    int x0 = (int)x0f; int x1 = min(x0 + 1, WW - 1);
    int y0 = (int)y0f; int y1 = min(y0 + 1, HH - 1);
    int z0 = (int)z0f; int z1 = min(z0 + 1, DD - 1);

    int zy00 = z0 * HW + y0 * WW;
    int zy01 = z0 * HW + y1 * WW;
    int zy10 = z1 * HW + y0 * WW;
    int zy11 = z1 * HW + y1 * WW;

    // 8 raw loads first (max MLP), then convert/lerp x -> y -> z.
    uint2 r000 = __ldg(hb + zy00 + x0);
    uint2 r001 = __ldg(hb + zy00 + x1);
    uint2 r010 = __ldg(hb + zy01 + x0);
    uint2 r011 = __ldg(hb + zy01 + x1);
    uint2 r100 = __ldg(hb + zy10 + x0);
    uint2 r101 = __ldg(hb + zy10 + x1);
    uint2 r110 = __ldg(hb + zy11 + x0);
    uint2 r111 = __ldg(hb + zy11 + x1);

    float3 c00 = lerp3(unpack_h4(r000), unpack_h4(r001), wx);
    float3 c01 = lerp3(unpack_h4(r010), unpack_h4(r011), wx);
    float3 c10 = lerp3(unpack_h4(r100), unpack_h4(r101), wx);
    float3 c11 = lerp3(unpack_h4(r110), unpack_h4(r111), wx);
    float3 c0 = lerp3(c00, c01, wy);
    float3 c1 = lerp3(c10, c11, wy);
    return lerp3(c0, c1, wz);
}

template <bool LAST>
__global__ void __launch_bounds__(256) expflow_step(const float* __restrict__ mx,
                                                    const float* __restrict__ my,
                                                    const float* __restrict__ mz,
                                                    const uint2* __restrict__ in16,
                                                    float* __restrict__ omx,
                                                    float* __restrict__ omy,
                                                    float* __restrict__ omz,
                                                    uint2* __restrict__ out16,
                                                    float* __restrict__ gout) {
    int t = blockIdx.x * blockDim.x + threadIdx.x;
    if (t >= NPAIR) return;
    int p = t * 2;
    int n = p / DHW;
    int s = p - n * DHW;
    int zz = s / HW;
    int rem = s - zz * HW;
    int yy = rem / WW;
    int xx = rem - yy * WW;  // even; pair never crosses a row (W=128)

    float2 cx = *reinterpret_cast<const float2*>(mx + p);
    float2 cy = *reinterpret_cast<const float2*>(my + p);
    float2 cz = *reinterpret_cast<const float2*>(mz + p);

    const uint2* hb = in16 + n * DHW;

    float3 s0 = sample_shadow(hb, xx,     yy, zz, cx.x, cy.x, cz.x);
    float3 s1 = sample_shadow(hb, xx + 1, yy, zz, cx.y, cy.y, cz.y);

    float2 rx = make_float2(cx.x + s0.x, cx.y + s1.x);
    float2 ry = make_float2(cy.x + s0.y, cy.y + s1.y);
    float2 rz = make_float2(cz.x + s0.z, cz.y + s1.z);

    if (LAST) {
        // Fused transpose back to [N, 3, D, H, W]; coalesced float2 per plane.
        float* ob = gout + (size_t)n * 3 * DHW + s;
        *reinterpret_cast<float2*>(ob) = rx;
        *reinterpret_cast<float2*>(ob + DHW) = ry;
        *reinterpret_cast<float2*>(ob + 2 * DHW) = rz;
    } else {
        *reinterpret_cast<float2*>(omx + p) = rx;
        *reinterpret_cast<float2*>(omy + p) = ry;
        *reinterpret_cast<float2*>(omz + p) = rz;
        uint2 h0 = pack_h4(rx.x, ry.x, rz.x);
        uint2 h1 = pack_h4(rx.y, ry.y, rz.y);
        *reinterpret_cast<uint4*>(out16 + p) = make_uint4(h0.x, h0.y, h1.x, h1.y);
    }
}

// ---------------------------------------------------------------------------
extern "C" void kernel_launch(void* const* d_in, const int* in_sizes, int n_in,
                              void* d_out, int out_size) {
    const float* x = (const float*)d_in[0];
    float* out = (float*)d_out;

    float *mx0, *my0, *mz0, *mx1, *my1, *mz1;
    uint2 *h0, *h1;
    cudaGetSymbolAddress((void**)&mx0, g_mx0);
    cudaGetSymbolAddress((void**)&my0, g_my0);
    cudaGetSymbolAddress((void**)&mz0, g_mz0);
    cudaGetSymbolAddress((void**)&mx1, g_mx1);
    cudaGetSymbolAddress((void**)&my1, g_my1);
    cudaGetSymbolAddress((void**)&mz1, g_mz1);
    cudaGetSymbolAddress((void**)&h0, g_h0);
    cudaGetSymbolAddress((void**)&h1, g_h1);

    const int threads = 256;
    const int blocks = (NPAIR + threads - 1) / threads;

    expflow_init<<<blocks, threads>>>(x, mx0, my0, mz0, h0);
    // 5 squaring steps: 4 ping-pong, last fused with output transpose.
    expflow_step<false><<<blocks, threads>>>(mx0, my0, mz0, h0, mx1, my1, mz1, h1, nullptr);
    expflow_step<false><<<blocks, threads>>>(mx1, my1, mz1, h1, mx0, my0, mz0, h0, nullptr);
    expflow_step<false><<<blocks, threads>>>(mx0, my0, mz0, h0, mx1, my1, mz1, h1, nullptr);
    expflow_step<false><<<blocks, threads>>>(mx1, my1, mz1, h1, mx0, my0, mz0, h0, nullptr);
    expflow_step<true><<<blocks, threads>>>(mx0, my0, mz0, h0, nullptr, nullptr, nullptr, nullptr, out);
}